// round 14
// baseline (speedup 1.0000x reference)
#include <cuda_runtime.h>
#include <cstdint>

// Problem constants (shapes are fixed by the dataset)
#define NODES 50000
#define FD    512          // feature dim == hidden dim
#define BN_EPS 1e-5f

// ---------------- device scratch (no allocations allowed) ----------------
__device__ __align__(16) float g_h[(size_t)NODES * FD];   // h = x + agg
__device__ __align__(16) float g_z[(size_t)NODES * FD];   // z = h @ W^T
__device__ float g_colsum[FD];
__device__ float g_colsumsq[FD];
__device__ float g_scale[FD];
__device__ float g_shift[FD];
__device__ int   g_is64;

// ---------------- kernel 1: h = x (copy), zero stats, detect edge dtype ----
__global__ void k_copy(const float4* __restrict__ x4, const int* __restrict__ ew,
                       long n4) {
    long i = (long)blockIdx.x * blockDim.x + threadIdx.x;
    long stride = (long)gridDim.x * blockDim.x;
    float4* h4 = reinterpret_cast<float4*>(g_h);
    for (long j = i; j < n4; j += stride) h4[j] = x4[j];
    if (i < FD) { g_colsum[i] = 0.f; g_colsumsq[i] = 0.f; }
    if (blockIdx.x == 0 && threadIdx.x == 0) {
        // int64 little-endian: high 32-bit words of nonneg indices are 0.
        int is64 = 1;
        for (int k = 1; k < 256; k += 2) {
            if (ew[k] != 0) { is64 = 0; break; }
        }
        g_is64 = is64;
    }
}

// ---------------- kernel 2: edge aggregation via vector atomics -----------
// One edge per 128-thread group (4 edges per 512-thread block).
__global__ void k_edges(const float4* __restrict__ x4, const int* __restrict__ ew,
                        int E) {
    int lane = threadIdx.x & 127;
    int e = blockIdx.x * 4 + (threadIdx.x >> 7);
    if (e >= E) return;
    int src, dst;
    if (g_is64) {
        const long long* e64 = reinterpret_cast<const long long*>(ew);
        src = (int)e64[e];
        dst = (int)e64[(size_t)E + e];
    } else {
        src = ew[e];
        dst = ew[(size_t)E + e];
    }
    float4 v = x4[(size_t)src * (FD / 4) + lane];
    float* p = g_h + (size_t)dst * FD + lane * 4;
    asm volatile("red.global.add.v4.f32 [%0], {%1,%2,%3,%4};"
                 :: "l"(p), "f"(v.x), "f"(v.y), "f"(v.z), "f"(v.w) : "memory");
}

// ---------------- kernel 3: tf32 tensor-core GEMM  z = h @ W^T ------------
// Block tile 128x128, BK=32, 2-stage cp.async pipeline, 8 warps (2m x 4n),
// warp tile 64x32 via mma.sync.m16n8k8.tf32. Shared stride 36 floats
// (36 % 32 == 4) makes every fragment LDS pattern conflict-free.
#define BM   128
#define BNT  128
#define BK   32
#define LDSW 36
#define SMEM_FLOATS (2 * BM * LDSW + 2 * BNT * LDSW)
#define SMEM_BYTES  (SMEM_FLOATS * 4)

__device__ __forceinline__ void cp16(float* dst, const float* src, bool pred) {
    uint32_t d = (uint32_t)__cvta_generic_to_shared(dst);
    int sz = pred ? 16 : 0;   // src-size 0 -> zero-fill 16B
    asm volatile("cp.async.cg.shared.global [%0], [%1], 16, %2;"
                 :: "r"(d), "l"(src), "r"(sz) : "memory");
}

__global__ void __launch_bounds__(256, 2)
k_gemm(const float* __restrict__ W, int M) {
    extern __shared__ float sm[];
    float* As = sm;                          // [2][BM][LDSW]
    float* Bs = sm + 2 * BM * LDSW;          // [2][BNT][LDSW]

    const int tid  = threadIdx.x;
    const int lane = tid & 31;
    const int warp = tid >> 5;
    const int g = lane >> 2;                 // groupID (0..7)
    const int t = lane & 3;                  // threadID_in_group (0..3)
    const int wm = (warp & 1) * 64;          // warp m-offset in block tile
    const int wn = (warp >> 1) * 32;         // warp n-offset
    const int bn = blockIdx.x * BNT;         // x = N dim (4 blocks) -> A reuse
    const int bm = blockIdx.y * BM;

    float c[4][4][4];
    #pragma unroll
    for (int i = 0; i < 4; i++)
        #pragma unroll
        for (int j = 0; j < 4; j++)
            #pragma unroll
            for (int r = 0; r < 4; r++) c[i][j][r] = 0.f;

    auto load_tiles = [&](int k0, int s) {
        float* as = As + s * BM * LDSW;
        float* bs = Bs + s * BNT * LDSW;
        #pragma unroll
        for (int it = 0; it < 4; it++) {
            int idx = tid + it * 256;        // 1024 float4 per tile
            int row = idx >> 3;
            int c4  = (idx & 7) * 4;
            int gm  = bm + row;
            bool p  = gm < M;
            const float* srcA = g_h + (size_t)(p ? gm : 0) * FD + k0 + c4;
            cp16(as + row * LDSW + c4, srcA, p);
            cp16(bs + row * LDSW + c4,
                 W + (size_t)(bn + row) * FD + k0 + c4, true);
        }
    };

    auto compute = [&](int s) {
        const float* as = As + s * BM * LDSW;
        const float* bs = Bs + s * BNT * LDSW;
        #pragma unroll
        for (int kk = 0; kk < 4; kk++) {
            const int k = kk * 8;
            uint32_t a[4][4], b[4][2];
            #pragma unroll
            for (int i = 0; i < 4; i++) {
                int r = wm + i * 16 + g;
                a[i][0] = __float_as_uint(as[r * LDSW + k + t]);
                a[i][1] = __float_as_uint(as[(r + 8) * LDSW + k + t]);
                a[i][2] = __float_as_uint(as[r * LDSW + k + t + 4]);
                a[i][3] = __float_as_uint(as[(r + 8) * LDSW + k + t + 4]);
            }
            #pragma unroll
            for (int j = 0; j < 4; j++) {
                int n = wn + j * 8 + g;
                b[j][0] = __float_as_uint(bs[n * LDSW + k + t]);
                b[j][1] = __float_as_uint(bs[n * LDSW + k + t + 4]);
            }
            #pragma unroll
            for (int i = 0; i < 4; i++)
                #pragma unroll
                for (int j = 0; j < 4; j++)
                    asm volatile(
                        "mma.sync.aligned.m16n8k8.row.col.f32.tf32.tf32.f32 "
                        "{%0,%1,%2,%3}, {%4,%5,%6,%7}, {%8,%9}, {%0,%1,%2,%3};"
                        : "+f"(c[i][j][0]), "+f"(c[i][j][1]),
                          "+f"(c[i][j][2]), "+f"(c[i][j][3])
                        : "r"(a[i][0]), "r"(a[i][1]), "r"(a[i][2]), "r"(a[i][3]),
                          "r"(b[j][0]), "r"(b[j][1]));
        }
    };

    load_tiles(0, 0);
    asm volatile("cp.async.commit_group;" ::: "memory");
    load_tiles(BK, 1);
    asm volatile("cp.async.commit_group;" ::: "memory");

    const int NC = FD / BK;  // 16
    for (int cd = 0; cd < NC; cd++) {
        asm volatile("cp.async.wait_group 1;" ::: "memory");
        __syncthreads();
        int s = cd & 1;
        compute(s);
        __syncthreads();
        if (cd + 2 < NC) load_tiles((cd + 2) * BK, s);
        asm volatile("cp.async.commit_group;" ::: "memory");
    }

    // Epilogue: c0,c1 -> (m0, n..n+1); c2,c3 -> (m0+8, n..n+1). Bias b cancels
    // under train-mode BatchNorm, so it is intentionally omitted.
    #pragma unroll
    for (int i = 0; i < 4; i++) {
        int m0 = bm + wm + i * 16 + g;
        #pragma unroll
        for (int j = 0; j < 4; j++) {
            int n = bn + wn + j * 8 + t * 2;
            if (m0 < M)
                *reinterpret_cast<float2*>(&g_z[(size_t)m0 * FD + n]) =
                    make_float2(c[i][j][0], c[i][j][1]);
            if (m0 + 8 < M)
                *reinterpret_cast<float2*>(&g_z[(size_t)(m0 + 8) * FD + n]) =
                    make_float2(c[i][j][2], c[i][j][3]);
        }
    }
}

// ---------------- kernel 4: per-column sum / sumsq -------------------------
__global__ void k_stats(int M) {
    int col = blockIdx.x * 256 + threadIdx.x;   // gridDim.x = FD/256
    float s = 0.f, q = 0.f;
    for (int r = blockIdx.y; r < M; r += gridDim.y) {
        float v = g_z[(size_t)r * FD + col];
        s += v;
        q += v * v;
    }
    atomicAdd(&g_colsum[col], s);
    atomicAdd(&g_colsumsq[col], q);
}

// ---------------- kernel 5: BN parameters ---------------------------------
__global__ void k_params(const float* __restrict__ gamma,
                         const float* __restrict__ beta, int M) {
    int c = threadIdx.x;
    float inv = 1.0f / (float)M;
    float mean = g_colsum[c] * inv;
    float var  = g_colsumsq[c] * inv - mean * mean;
    float sc   = gamma[c] * rsqrtf(var + BN_EPS);
    g_scale[c] = sc;
    g_shift[c] = beta[c] - mean * sc;
}

// ---------------- kernel 6: out = z * scale + shift ------------------------
__global__ void k_norm(float4* __restrict__ out, long n4) {
    long i = (long)blockIdx.x * blockDim.x + threadIdx.x;
    long stride = (long)gridDim.x * blockDim.x;
    const float4* z4 = reinterpret_cast<const float4*>(g_z);
    const float4* sc4 = reinterpret_cast<const float4*>(g_scale);
    const float4* sh4 = reinterpret_cast<const float4*>(g_shift);
    for (long j = i; j < n4; j += stride) {
        int c4 = (int)(j & (FD / 4 - 1));
        float4 sc = sc4[c4];
        float4 sh = sh4[c4];
        float4 v = z4[j];
        out[j] = make_float4(v.x * sc.x + sh.x, v.y * sc.y + sh.y,
                             v.z * sc.z + sh.z, v.w * sc.w + sh.w);
    }
}

// ---------------- launch ----------------------------------------------------
extern "C" void kernel_launch(void* const* d_in, const int* in_sizes, int n_in,
                              void* d_out, int out_size) {
    const float* x     = (const float*)d_in[0];
    const int*   ew    = (const int*)d_in[1];   // edge_index words (dtype detected on device)
    const float* W     = (const float*)d_in[3];
    const float* gamma = (const float*)d_in[5];
    const float* beta  = (const float*)d_in[6];

    int M = in_sizes[0] / FD;     // 50000
    int E = in_sizes[1] / 2;      // 160000
    long n4 = (long)M * (FD / 4);

    k_copy<<<4096, 256>>>((const float4*)x, ew, n4);
    k_edges<<<(E + 3) / 4, 512>>>((const float4*)x, ew, E);

    cudaFuncSetAttribute(k_gemm, cudaFuncAttributeMaxDynamicSharedMemorySize,
                         SMEM_BYTES);
    dim3 gg(FD / BNT, (M + BM - 1) / BM);
    k_gemm<<<gg, 256, SMEM_BYTES>>>(W, M);

    k_stats<<<dim3(FD / 256, 256), 256>>>(M);
    k_params<<<1, FD>>>(gamma, beta, M);
    k_norm<<<4096, 256>>>((float4*)d_out, n4);
}

// round 15
// speedup vs baseline: 1.0025x; 1.0025x over previous
#include <cuda_runtime.h>
#include <cstdint>

// Problem constants (shapes are fixed by the dataset)
#define NODES 50000
#define FD    512          // feature dim == hidden dim
#define BN_EPS 1e-5f

// ---------------- device scratch (no allocations allowed) ----------------
__device__ __align__(16) float g_h[(size_t)NODES * FD];   // h = x + agg
__device__ __align__(16) float g_z[(size_t)NODES * FD];   // z = h @ W^T
__device__ float g_colsum[FD];
__device__ float g_colsumsq[FD];
__device__ float g_scale[FD];
__device__ float g_shift[FD];
__device__ int   g_is64;

// ---------------- kernel 1: h = x (copy), zero stats, detect edge dtype ----
__global__ void k_copy(const float4* __restrict__ x4, const int* __restrict__ ew,
                       long n4) {
    long i = (long)blockIdx.x * blockDim.x + threadIdx.x;
    long stride = (long)gridDim.x * blockDim.x;
    float4* h4 = reinterpret_cast<float4*>(g_h);
    for (long j = i; j < n4; j += stride) h4[j] = x4[j];
    if (i < FD) { g_colsum[i] = 0.f; g_colsumsq[i] = 0.f; }
    if (blockIdx.x == 0 && threadIdx.x == 0) {
        // int64 little-endian: high 32-bit words of nonneg indices are 0.
        int is64 = 1;
        for (int k = 1; k < 256; k += 2) {
            if (ew[k] != 0) { is64 = 0; break; }
        }
        g_is64 = is64;
    }
}

// ---------------- kernel 2: edge aggregation via vector atomics -----------
// One edge per 128-thread group (4 edges per 512-thread block).
__global__ void k_edges(const float4* __restrict__ x4, const int* __restrict__ ew,
                        int E) {
    int lane = threadIdx.x & 127;
    int e = blockIdx.x * 4 + (threadIdx.x >> 7);
    if (e >= E) return;
    int src, dst;
    if (g_is64) {
        const long long* e64 = reinterpret_cast<const long long*>(ew);
        src = (int)e64[e];
        dst = (int)e64[(size_t)E + e];
    } else {
        src = ew[e];
        dst = ew[(size_t)E + e];
    }
    float4 v = x4[(size_t)src * (FD / 4) + lane];
    float* p = g_h + (size_t)dst * FD + lane * 4;
    asm volatile("red.global.add.v4.f32 [%0], {%1,%2,%3,%4};"
                 :: "l"(p), "f"(v.x), "f"(v.y), "f"(v.z), "f"(v.w) : "memory");
}

// ---------------- kernel 3: tf32 tensor-core GEMM  z = h @ W^T ------------
// Block tile 128x128, BK=32, 2-stage cp.async pipeline, 8 warps (2m x 4n),
// warp tile 64x32 via mma.sync.m16n8k8.tf32. Shared stride 36 floats
// (36 % 32 == 4) makes every fragment LDS pattern conflict-free.
#define BM   128
#define BNT  128
#define BK   32
#define LDSW 36
#define SMEM_FLOATS (2 * BM * LDSW + 2 * BNT * LDSW)
#define SMEM_BYTES  (SMEM_FLOATS * 4)

__device__ __forceinline__ void cp16(float* dst, const float* src, bool pred) {
    uint32_t d = (uint32_t)__cvta_generic_to_shared(dst);
    int sz = pred ? 16 : 0;   // src-size 0 -> zero-fill 16B
    asm volatile("cp.async.cg.shared.global [%0], [%1], 16, %2;"
                 :: "r"(d), "l"(src), "r"(sz) : "memory");
}

__global__ void __launch_bounds__(256, 2)
k_gemm(const float* __restrict__ W, int M) {
    extern __shared__ float sm[];
    float* As = sm;                          // [2][BM][LDSW]
    float* Bs = sm + 2 * BM * LDSW;          // [2][BNT][LDSW]

    const int tid  = threadIdx.x;
    const int lane = tid & 31;
    const int warp = tid >> 5;
    const int g = lane >> 2;                 // groupID (0..7)
    const int t = lane & 3;                  // threadID_in_group (0..3)
    const int wm = (warp & 1) * 64;          // warp m-offset in block tile
    const int wn = (warp >> 1) * 32;         // warp n-offset
    const int bn = blockIdx.x * BNT;         // x = N dim (4 blocks) -> A reuse
    const int bm = blockIdx.y * BM;

    float c[4][4][4];
    #pragma unroll
    for (int i = 0; i < 4; i++)
        #pragma unroll
        for (int j = 0; j < 4; j++)
            #pragma unroll
            for (int r = 0; r < 4; r++) c[i][j][r] = 0.f;

    auto load_tiles = [&](int k0, int s) {
        float* as = As + s * BM * LDSW;
        float* bs = Bs + s * BNT * LDSW;
        #pragma unroll
        for (int it = 0; it < 4; it++) {
            int idx = tid + it * 256;        // 1024 float4 per tile
            int row = idx >> 3;
            int c4  = (idx & 7) * 4;
            int gm  = bm + row;
            bool p  = gm < M;
            const float* srcA = g_h + (size_t)(p ? gm : 0) * FD + k0 + c4;
            cp16(as + row * LDSW + c4, srcA, p);
            cp16(bs + row * LDSW + c4,
                 W + (size_t)(bn + row) * FD + k0 + c4, true);
        }
    };

    auto compute = [&](int s) {
        const float* as = As + s * BM * LDSW;
        const float* bs = Bs + s * BNT * LDSW;
        #pragma unroll
        for (int kk = 0; kk < 4; kk++) {
            const int k = kk * 8;
            uint32_t a[4][4], b[4][2];
            #pragma unroll
            for (int i = 0; i < 4; i++) {
                int r = wm + i * 16 + g;
                a[i][0] = __float_as_uint(as[r * LDSW + k + t]);
                a[i][1] = __float_as_uint(as[(r + 8) * LDSW + k + t]);
                a[i][2] = __float_as_uint(as[r * LDSW + k + t + 4]);
                a[i][3] = __float_as_uint(as[(r + 8) * LDSW + k + t + 4]);
            }
            #pragma unroll
            for (int j = 0; j < 4; j++) {
                int n = wn + j * 8 + g;
                b[j][0] = __float_as_uint(bs[n * LDSW + k + t]);
                b[j][1] = __float_as_uint(bs[n * LDSW + k + t + 4]);
            }
            #pragma unroll
            for (int i = 0; i < 4; i++)
                #pragma unroll
                for (int j = 0; j < 4; j++)
                    asm volatile(
                        "mma.sync.aligned.m16n8k8.row.col.f32.tf32.tf32.f32 "
                        "{%0,%1,%2,%3}, {%4,%5,%6,%7}, {%8,%9}, {%0,%1,%2,%3};"
                        : "+f"(c[i][j][0]), "+f"(c[i][j][1]),
                          "+f"(c[i][j][2]), "+f"(c[i][j][3])
                        : "r"(a[i][0]), "r"(a[i][1]), "r"(a[i][2]), "r"(a[i][3]),
                          "r"(b[j][0]), "r"(b[j][1]));
        }
    };

    load_tiles(0, 0);
    asm volatile("cp.async.commit_group;" ::: "memory");
    load_tiles(BK, 1);
    asm volatile("cp.async.commit_group;" ::: "memory");

    const int NC = FD / BK;  // 16
    for (int cd = 0; cd < NC; cd++) {
        asm volatile("cp.async.wait_group 1;" ::: "memory");
        __syncthreads();
        int s = cd & 1;
        compute(s);
        __syncthreads();
        if (cd + 2 < NC) load_tiles((cd + 2) * BK, s);
        asm volatile("cp.async.commit_group;" ::: "memory");
    }

    // Epilogue: c0,c1 -> (m0, n..n+1); c2,c3 -> (m0+8, n..n+1). Bias b cancels
    // under train-mode BatchNorm, so it is intentionally omitted.
    #pragma unroll
    for (int i = 0; i < 4; i++) {
        int m0 = bm + wm + i * 16 + g;
        #pragma unroll
        for (int j = 0; j < 4; j++) {
            int n = bn + wn + j * 8 + t * 2;
            if (m0 < M)
                *reinterpret_cast<float2*>(&g_z[(size_t)m0 * FD + n]) =
                    make_float2(c[i][j][0], c[i][j][1]);
            if (m0 + 8 < M)
                *reinterpret_cast<float2*>(&g_z[(size_t)(m0 + 8) * FD + n]) =
                    make_float2(c[i][j][2], c[i][j][3]);
        }
    }
}

// ---------------- kernel 4: per-column sum / sumsq -------------------------
__global__ void k_stats(int M) {
    int col = blockIdx.x * 256 + threadIdx.x;   // gridDim.x = FD/256
    float s = 0.f, q = 0.f;
    for (int r = blockIdx.y; r < M; r += gridDim.y) {
        float v = g_z[(size_t)r * FD + col];
        s += v;
        q += v * v;
    }
    atomicAdd(&g_colsum[col], s);
    atomicAdd(&g_colsumsq[col], q);
}

// ---------------- kernel 5: BN parameters ---------------------------------
__global__ void k_params(const float* __restrict__ gamma,
                         const float* __restrict__ beta, int M) {
    int c = threadIdx.x;
    float inv = 1.0f / (float)M;
    float mean = g_colsum[c] * inv;
    float var  = g_colsumsq[c] * inv - mean * mean;
    float sc   = gamma[c] * rsqrtf(var + BN_EPS);
    g_scale[c] = sc;
    g_shift[c] = beta[c] - mean * sc;
}

// ---------------- kernel 6: out = z * scale + shift ------------------------
__global__ void k_norm(float4* __restrict__ out, long n4) {
    long i = (long)blockIdx.x * blockDim.x + threadIdx.x;
    long stride = (long)gridDim.x * blockDim.x;
    const float4* z4 = reinterpret_cast<const float4*>(g_z);
    const float4* sc4 = reinterpret_cast<const float4*>(g_scale);
    const float4* sh4 = reinterpret_cast<const float4*>(g_shift);
    for (long j = i; j < n4; j += stride) {
        int c4 = (int)(j & (FD / 4 - 1));
        float4 sc = sc4[c4];
        float4 sh = sh4[c4];
        float4 v = z4[j];
        out[j] = make_float4(v.x * sc.x + sh.x, v.y * sc.y + sh.y,
                             v.z * sc.z + sh.z, v.w * sc.w + sh.w);
    }
}

// ---------------- launch ----------------------------------------------------
extern "C" void kernel_launch(void* const* d_in, const int* in_sizes, int n_in,
                              void* d_out, int out_size) {
    const float* x     = (const float*)d_in[0];
    const int*   ew    = (const int*)d_in[1];   // edge_index words (dtype detected on device)
    const float* W     = (const float*)d_in[3];
    const float* gamma = (const float*)d_in[5];
    const float* beta  = (const float*)d_in[6];

    int M = in_sizes[0] / FD;     // 50000
    int E = in_sizes[1] / 2;      // 160000
    long n4 = (long)M * (FD / 4);

    k_copy<<<4096, 256>>>((const float4*)x, ew, n4);
    k_edges<<<(E + 3) / 4, 512>>>((const float4*)x, ew, E);

    cudaFuncSetAttribute(k_gemm, cudaFuncAttributeMaxDynamicSharedMemorySize,
                         SMEM_BYTES);
    dim3 gg(FD / BNT, (M + BM - 1) / BM);
    k_gemm<<<gg, 256, SMEM_BYTES>>>(W, M);

    k_stats<<<dim3(FD / 256, 256), 256>>>(M);
    k_params<<<1, FD>>>(gamma, beta, M);
    k_norm<<<4096, 256>>>((float4*)d_out, n4);
}